// round 16
// baseline (speedup 1.0000x reference)
#include <cuda_runtime.h>

// ---------------- problem constants ----------------
#define BATCH 4
#define SEQ   8192
#define NDIM  512
#define HEADS 8
#define DH    64
#define ML    256
#define LP    32
#define BH    32
#define MTOK  32768
#define KCONV 33
#define SPLIT 8
#define PINV_BLOCKS 128

// ---------------- scratch ----------------
__device__ float g_q[16777216];      // [BH, SEQ, DH]  tf32-rounded (q pre-scaled)
__device__ float g_k[16777216];      // tf32-rounded
__device__ float g_v[16777216];      // tf32-rounded
__device__ float g_ql[524288];       // tf32-rounded
__device__ float g_kl[524288];       // tf32-rounded
__device__ float g_attn2[2097152];   // rounded attn2
__device__ float g_z0[2097152];
__device__ float g_z1[2097152];
__device__ float g_xz[2097152];
__device__ float g_t[2097152];       // (step0: rounded w_qkv^T [1536][512]) then pinv scratch
__device__ float g_u[2097152];
__device__ float g_a3v[524288];
__device__ float g_wm[524288];       // tf32-rounded
__device__ float g_y[16777216];      // (step0: rounded x) then y (rounded)
__device__ float g_wout[262144];     // rounded w_out^T [512][512]
__device__ float g_part_o[4194304];
__device__ float g_part_m[65536];
__device__ float g_part_s[65536];
__device__ float g_csp[65536];
__device__ float g_scal[2] = {0.f, 0.f};
__device__ unsigned g_cnt[BH];
__device__ volatile unsigned g_gen[BH];

// ================= helpers =================
__device__ __forceinline__ float tf32r(float f)
{
    unsigned u;
    asm("cvt.rna.tf32.f32 %0, %1;" : "=r"(u) : "f"(f));
    return __uint_as_float(u);
}
__device__ __forceinline__ float4 tf32r4(float4 v)
{
    float4 w;
    w.x = tf32r(v.x); w.y = tf32r(v.y); w.z = tf32r(v.z); w.w = tf32r(v.w);
    return w;
}

__device__ __forceinline__ void cp16(void* s, const void* g)
{
    unsigned sa = (unsigned)__cvta_generic_to_shared(s);
    asm volatile("cp.async.cg.shared.global [%0], [%1], 16;" :: "r"(sa), "l"(g));
}
__device__ __forceinline__ void cp_commit() { asm volatile("cp.async.commit_group;"); }
__device__ __forceinline__ void cp_wait0()  { asm volatile("cp.async.wait_group 0;"); }

__device__ __forceinline__ void mma8(float* c, const unsigned* a, unsigned b0, unsigned b1)
{
    asm volatile("mma.sync.aligned.m16n8k8.row.col.f32.tf32.tf32.f32 "
                 "{%0,%1,%2,%3},{%4,%5,%6,%7},{%8,%9},{%0,%1,%2,%3};"
                 : "+f"(c[0]), "+f"(c[1]), "+f"(c[2]), "+f"(c[3])
                 : "r"(a[0]), "r"(a[1]), "r"(a[2]), "r"(a[3]), "r"(b0), "r"(b1));
}

__device__ __forceinline__ void ldsm4(unsigned* r, unsigned saddr)
{
    asm volatile("ldmatrix.sync.aligned.m8n8.x4.shared.b16 {%0,%1,%2,%3}, [%4];"
                 : "=r"(r[0]), "=r"(r[1]), "=r"(r[2]), "=r"(r[3]) : "r"(saddr));
}

// per-batch 4-block barrier (proven deadlock-free: 128 blocks <= 148 SMs at 1/SM)
__device__ __forceinline__ void group_sync(int bz)
{
    __syncthreads();
    __threadfence();
    if (threadIdx.x == 0) {
        unsigned gen = g_gen[bz];
        if (atomicAdd(&g_cnt[bz], 1u) == 3u) {
            atomicExch(&g_cnt[bz], 0u);
            __threadfence();
            g_gen[bz] = gen + 1;
        } else {
            while (g_gen[bz] == gen) __nanosleep(32);
        }
    }
    __syncthreads();
}

// ---------------- tf32 rounding preludes ----------------
__global__ void round_kernel(float* __restrict__ dst, const float* __restrict__ src, int n4)
{
    int i = blockIdx.x * 256 + threadIdx.x;
    if (i < n4) ((float4*)dst)[i] = tf32r4(((const float4*)src)[i]);
}

// dst[Cc][R] = tf32r(src[R][Cc]) via 32x32 smem tiles; grid (Cc/32, R/32)
__global__ void round_tr_kernel(float* __restrict__ dst, const float* __restrict__ src, int R, int Cc)
{
    __shared__ float ts[32][33];
    int c0 = blockIdx.x * 32, r0 = blockIdx.y * 32;
    int lx = threadIdx.x & 31, ly = threadIdx.x >> 5;
    #pragma unroll
    for (int i = 0; i < 4; i++)
        ts[ly + i * 8][lx] = src[(long long)(r0 + ly + i * 8) * Cc + c0 + lx];
    __syncthreads();
    #pragma unroll
    for (int i = 0; i < 4; i++)
        dst[(long long)(c0 + ly + i * 8) * R + r0 + lx] = tf32r(ts[lx][ly + i * 8]);
}

// ================= TF32 GEMM: k32, 2-stage, ldmatrix fragments, B TRANSPOSED ======
#define ASTG 4608   // 128*36
template<int EPI>
__global__ void __launch_bounds__(256, 2) tgemm_kernel(
    const float* __restrict__ A, const float* __restrict__ BT,
    float* __restrict__ C,
    int K, int lda, int ldb, int ldc,
    float alpha,
    const float* __restrict__ bias, const float* __restrict__ resid)
{
    extern __shared__ float smem[];
    float* As = smem;
    float* Bs = smem + 2 * ASTG;

    const int m0 = blockIdx.y * 128;
    const int n0 = blockIdx.x * 128;
    const int tid = threadIdx.x;
    const int warp = tid >> 5, lane = tid & 31;
    const int gid = lane >> 2, tig = lane & 3;
    const int wm = warp >> 1, wn = warp & 1;

    auto stage = [&](int s, int kk) {
        float* Ab = As + s * ASTG;
        float* Bb = Bs + s * ASTG;
        #pragma unroll
        for (int i = 0; i < 4; i++) {
            int slot = tid + i * 256;
            int r = slot >> 3, kq = (slot & 7) << 2;
            cp16(&Ab[r * 36 + kq], &A[(long long)(m0 + r) * lda + kk + kq]);
            cp16(&Bb[r * 36 + kq], &BT[(long long)(n0 + r) * ldb + kk + kq]);
        }
    };

    float acc[2][8][4] = {};

    stage(0, 0);
    cp_commit();

    const unsigned sAb = (unsigned)__cvta_generic_to_shared(As);
    const unsigned sBb = (unsigned)__cvta_generic_to_shared(Bs);
    const unsigned aoff = (((wm * 32 + (lane & 15)) * 36) + ((lane >> 4) << 2)) * 4u;
    const int brow = (lane & 7) + ((lane >> 4) << 3);
    const unsigned boff = (((wn * 64 + brow) * 36) + (((lane >> 3) & 1) << 2)) * 4u;

    int buf = 0;
    for (int k0 = 0; k0 < K; k0 += 32) {
        cp_wait0();
        __syncthreads();
        if (k0 + 32 < K) { stage(buf ^ 1, k0 + 32); cp_commit(); }

        unsigned ab = sAb + (unsigned)(buf * ASTG * 4);
        unsigned bb = sBb + (unsigned)(buf * ASTG * 4);
        #pragma unroll
        for (int s = 0; s < 4; s++) {
            const unsigned kb4 = s * 32;
            unsigned af[2][4], bf[8][2];
            ldsm4(af[0], ab + aoff + kb4);
            ldsm4(af[1], ab + aoff + 16u * 36u * 4u + kb4);
            #pragma unroll
            for (int np = 0; np < 4; np++) {
                unsigned t[4];
                ldsm4(t, bb + boff + (unsigned)(np * 16 * 36 * 4) + kb4);
                bf[np * 2][0]     = t[0];
                bf[np * 2][1]     = t[1];
                bf[np * 2 + 1][0] = t[2];
                bf[np * 2 + 1][1] = t[3];
            }
            #pragma unroll
            for (int mf = 0; mf < 2; mf++)
                #pragma unroll
                for (int nf = 0; nf < 8; nf++)
                    mma8(acc[mf][nf], af[mf], bf[nf][0], bf[nf][1]);
        }
        buf ^= 1;
    }

    #pragma unroll
    for (int mf = 0; mf < 2; mf++) {
        #pragma unroll
        for (int nf = 0; nf < 8; nf++) {
            int r0 = m0 + wm * 32 + mf * 16 + gid;
            int c0 = n0 + wn * 64 + nf * 8 + tig * 2;
            float v00 = alpha * acc[mf][nf][0];
            float v01 = alpha * acc[mf][nf][1];
            float v10 = alpha * acc[mf][nf][2];
            float v11 = alpha * acc[mf][nf][3];

            if (EPI == 0) {
                long long o0 = (long long)r0 * ldc + c0;
                long long o1 = (long long)(r0 + 8) * ldc + c0;
                if (bias)  { v00 += bias[c0]; v01 += bias[c0 + 1]; v10 += bias[c0]; v11 += bias[c0 + 1]; }
                if (resid) { v00 += resid[o0]; v01 += resid[o0 + 1]; v10 += resid[o1]; v11 += resid[o1 + 1]; }
                C[o0] = v00; C[o0 + 1] = v01;
                C[o1] = v10; C[o1 + 1] = v11;
            } else {
                int sec = c0 >> 9;
                int rem = c0 & 511;
                int h = rem >> 6, dh = rem & 63;
                #pragma unroll
                for (int rr = 0; rr < 2; rr++) {
                    int gm = r0 + rr * 8;
                    int b = gm >> 13, n = gm & 8191;
                    long long off = (((long long)(b * HEADS + h)) * SEQ + n) * DH + dh;
                    float a0 = rr ? v10 : v00;
                    float a1 = rr ? v11 : v01;
                    if (sec == 0)      { g_q[off] = tf32r(a0 * 0.125f); g_q[off + 1] = tf32r(a1 * 0.125f); }
                    else if (sec == 1) { g_k[off] = tf32r(a0);          g_k[off + 1] = tf32r(a1); }
                    else               { g_v[off] = tf32r(a0);          g_v[off + 1] = tf32r(a1); }
                }
            }
        }
    }
}

// ================= fused Newton-Schulz pinv: 512 thr/block, 128 blocks ============
// Block tile 128x128 (same as R14), 16 warps (4m x 4n), warp tile 32x32.
// Same k-order per output element as R14 -> bit-identical results.
#define BSTG 4352   // 32*136
__device__ __forceinline__ void gemm_tile256(
    float* As, float* Bs,
    const float* __restrict__ A, const float* __restrict__ B,
    float* __restrict__ C, float* __restrict__ D,
    float alpha, float diag, int m0, int n0)
{
    const int tid = threadIdx.x;
    const int warp = tid >> 5, lane = tid & 31;
    const int gid = lane >> 2, tig = lane & 3;
    const int wm = warp >> 2, wn = warp & 3;   // 4 x 4 warps

    auto stage = [&](int s, int kk) {
        float* Ab = As + s * ASTG;
        float* Bb = Bs + s * BSTG;
        #pragma unroll
        for (int i = 0; i < 2; i++) {
            int slot = tid + i * 512;
            int ar = slot >> 3, akq = (slot & 7) << 2;
            cp16(&Ab[ar * 36 + akq], &A[(m0 + ar) * 256 + kk + akq]);
            int br = slot >> 5, bnq = (slot & 31) << 2;
            cp16(&Bb[br * 136 + bnq], &B[(kk + br) * 256 + n0 + bnq]);
        }
    };

    float acc[2][4][4] = {};

    stage(0, 0);
    cp_commit();

    const unsigned sAb = (unsigned)__cvta_generic_to_shared(As);
    const unsigned aoff = (((wm * 32 + (lane & 15)) * 36) + ((lane >> 4) << 2)) * 4u;

    int buf = 0;
    for (int k0 = 0; k0 < 256; k0 += 32) {
        cp_wait0();
        __syncthreads();
        if (k0 + 32 < 256) { stage(buf ^ 1, k0 + 32); cp_commit(); }

        unsigned ab = sAb + (unsigned)(buf * ASTG * 4);
        float* Bb = Bs + buf * BSTG;
        #pragma unroll
        for (int s = 0; s < 4; s++) {
            const int kb = s * 8;
            unsigned af[2][4], bf[4][2];
            ldsm4(af[0], ab + aoff + (unsigned)(kb * 4));
            ldsm4(af[1], ab + aoff + 16u * 36u * 4u + (unsigned)(kb * 4));
            #pragma unroll
            for (int nf = 0; nf < 4; nf++) {
                int c = wn * 32 + nf * 8 + gid;
                bf[nf][0] = __float_as_uint(Bb[(kb + tig) * 136 + c]);
                bf[nf][1] = __float_as_uint(Bb[(kb + tig + 4) * 136 + c]);
            }
            #pragma unroll
            for (int mf = 0; mf < 2; mf++)
                #pragma unroll
                for (int nf = 0; nf < 4; nf++)
                    mma8(acc[mf][nf], af[mf], bf[nf][0], bf[nf][1]);
        }
        buf ^= 1;
    }

    #pragma unroll
    for (int mf = 0; mf < 2; mf++)
        #pragma unroll
        for (int nf = 0; nf < 4; nf++) {
            int r0 = m0 + wm * 32 + mf * 16 + gid;
            int c0 = n0 + wn * 32 + nf * 8 + tig * 2;
            float v00 = alpha * acc[mf][nf][0];
            float v01 = alpha * acc[mf][nf][1];
            float v10 = alpha * acc[mf][nf][2];
            float v11 = alpha * acc[mf][nf][3];
            int o0 = r0 * 256 + c0;
            int o1 = (r0 + 8) * 256 + c0;
            if (C) {
                C[o0] = tf32r(v00); C[o0 + 1] = tf32r(v01);
                C[o1] = tf32r(v10); C[o1 + 1] = tf32r(v11);
            }
            if (D) {
                D[o0]     = tf32r((r0 == c0         ? diag : 0.f) - v00);
                D[o0 + 1] = tf32r((r0 == c0 + 1     ? diag : 0.f) - v01);
                D[o1]     = tf32r((r0 + 8 == c0     ? diag : 0.f) - v10);
                D[o1 + 1] = tf32r((r0 + 8 == c0 + 1 ? diag : 0.f) - v11);
            }
        }
}

__global__ void __launch_bounds__(512, 1) pinv_fused_kernel()
{
    extern __shared__ float smem[];
    float* As = smem;
    float* Bs = smem + 2 * ASTG;

    const int bx = blockIdx.x;            // 0..127
    const int bz = bx >> 2;               // 32 batches, 4 blocks each
    const int m0 = ((bx >> 1) & 1) * 128;
    const int n0 = (bx & 1) * 128;

    float* a2 = g_attn2 + bz * 65536;
    float* xz = g_xz + bz * 65536;
    float* tt = g_t  + bz * 65536;
    float* uu = g_u  + bz * 65536;
    float* zc = g_z0 + bz * 65536;
    float* zn = g_z1 + bz * 65536;

    for (int it = 0; it < 6; it++) {
        gemm_tile256(As, Bs, a2, zc, xz, tt, 1.f, 7.f, m0, n0);
        group_sync(bz);
        gemm_tile256(As, Bs, xz, tt, nullptr, uu, 1.f, 15.f, m0, n0);
        group_sync(bz);
        gemm_tile256(As, Bs, xz, uu, nullptr, tt, 1.f, 13.f, m0, n0);
        group_sync(bz);
        gemm_tile256(As, Bs, zc, tt, zn, nullptr, 0.25f, 0.f, m0, n0);
        group_sync(bz);
        float* tmp = zc; zc = zn; zn = tmp;
    }
}

// ---------------- small SIMT GEMM: wm = z @ a3v ----------------
__global__ void gemm_wm_kernel()
{
    int bz = blockIdx.z;
    const float* A = g_z0 + (long long)bz * 65536;
    const float* B = g_a3v + (long long)bz * ML * DH;
    float* C = g_wm + (long long)bz * ML * DH;

    __shared__ float As[16][68];
    __shared__ float Bs[16][68];

    const int tid = threadIdx.x;
    const int tx = tid & 15, ty = tid >> 4;
    const int m0 = blockIdx.y * 64;

    float acc[4][4] = {};
    for (int k0 = 0; k0 < ML; k0 += 16) {
        #pragma unroll
        for (int i = tid; i < 1024; i += 256) {
            int m = i >> 4, kk = i & 15;
            As[kk][m] = A[(m0 + m) * ML + k0 + kk];
        }
        #pragma unroll
        for (int i = tid; i < 1024; i += 256) {
            int kk = i >> 6, n = i & 63;
            Bs[kk][n] = B[(k0 + kk) * DH + n];
        }
        __syncthreads();
        #pragma unroll
        for (int kk = 0; kk < 16; kk++) {
            float a[4], bb[4];
            #pragma unroll
            for (int i = 0; i < 4; i++) a[i] = As[kk][ty * 4 + i];
            #pragma unroll
            for (int j = 0; j < 4; j++) bb[j] = Bs[kk][tx * 4 + j];
            #pragma unroll
            for (int i = 0; i < 4; i++)
                #pragma unroll
                for (int j = 0; j < 4; j++)
                    acc[i][j] = fmaf(a[i], bb[j], acc[i][j]);
        }
        __syncthreads();
    }
    #pragma unroll
    for (int i = 0; i < 4; i++)
        #pragma unroll
        for (int j = 0; j < 4; j++)
            C[(m0 + ty * 4 + i) * DH + tx * 4 + j] = tf32r(acc[i][j]);
}

// ---------------- landmark mean pooling ----------------
__global__ void pool_kernel()
{
    long long idx = (long long)blockIdx.x * 256 + threadIdx.x;
    if (idx >= 524288LL) return;
    int dh = idx & 63;
    int mi = (int)((idx >> 6) & 255);
    int bh = (int)(idx >> 14);
    const float* q = g_q + ((long long)bh * SEQ + mi * LP) * DH + dh;
    const float* k = g_k + ((long long)bh * SEQ + mi * LP) * DH + dh;
    float sq = 0.f, sk = 0.f;
    #pragma unroll
    for (int j = 0; j < LP; j++) { sq += q[j * DH]; sk += k[j * DH]; }
    g_ql[idx] = tf32r(sq * (1.f / LP));
    g_kl[idx] = tf32r(sk * (1.f / LP));
}

// ---------------- fused attn2 = softmax(ql @ kl^T) ----------
__global__ void attn2_fused_kernel()
{
    extern __shared__ float sm[];
    float* QsT = sm;
    float* Bt  = sm + 4352;
    float* Lg  = sm + 8704;
    float* inv = sm + 8704 + 16640;

    int mt = blockIdx.x;
    int bh = blockIdx.y;
    int tid = threadIdx.x;
    int tx = tid & 15, ty = tid >> 4;

    const float* qlb = g_ql + ((long long)bh * ML + mt * 64) * DH;
    const float* klb = g_kl + (long long)bh * ML * DH;

    for (int i = tid; i < 4096; i += 256) {
        int row = i >> 6, dh = i & 63;
        QsT[dh * 68 + row] = qlb[row * 64 + dh];
    }

    for (int lt = 0; lt < 4; lt++) {
        __syncthreads();
        for (int i = tid; i < 4096; i += 256) {
            int n = i >> 6, dh = i & 63;
            Bt[dh * 68 + n] = klb[(lt * 64 + n) * 64 + dh];
        }
        __syncthreads();
        float s2[4][4] = {};
        #pragma unroll
        for (int kk = 0; kk < 64; kk++) {
            float a[4], b[4];
            #pragma unroll
            for (int i = 0; i < 4; i++) a[i] = QsT[kk * 68 + ty * 4 + i];
            #pragma unroll
            for (int j = 0; j < 4; j++) b[j] = Bt[kk * 68 + tx * 4 + j];
            #pragma unroll
            for (int i = 0; i < 4; i++)
                #pragma unroll
                for (int j = 0; j < 4; j++)
                    s2[i][j] = fmaf(a[i], b[j], s2[i][j]);
        }
        #pragma unroll
        for (int i = 0; i < 4; i++)
            #pragma unroll
            for (int j = 0; j < 4; j++)
                Lg[(ty * 4 + i) * 260 + lt * 64 + tx * 4 + j] = s2[i][j];
    }
    __syncthreads();

    {
        int r = tid >> 2, c0 = (tid & 3) * 64;
        float mx = -1e30f;
        for (int c = 0; c < 64; c++) mx = fmaxf(mx, Lg[r * 260 + c0 + c]);
        mx = fmaxf(mx, __shfl_xor_sync(0xffffffffu, mx, 1));
        mx = fmaxf(mx, __shfl_xor_sync(0xffffffffu, mx, 2));
        float sum = 0.f;
        for (int c = 0; c < 64; c++) {
            float e = __expf(Lg[r * 260 + c0 + c] - mx);
            Lg[r * 260 + c0 + c] = e;
            sum += e;
        }
        sum += __shfl_xor_sync(0xffffffffu, sum, 1);
        sum += __shfl_xor_sync(0xffffffffu, sum, 2);
        if ((tid & 3) == 0) inv[r] = 1.f / sum;
    }
    __syncthreads();

    float* ob = g_attn2 + ((long long)bh * ML + mt * 64) * ML;
    for (int i = tid; i < 16384; i += 256) {
        int row = i >> 8, col = i & 255;
        ob[row * 256 + col] = tf32r(Lg[row * 260 + col] * inv[row]);
    }
}

// ---------------- pinv scale ----------------
__global__ void pinv_scale_part()
{
    int bz = blockIdx.x, rc = blockIdx.y, j = threadIdx.x;
    const float* p = g_attn2 + (long long)bz * 65536 + rc * 32 * 256;
    float cs = 0.f;
    #pragma unroll
    for (int i = 0; i < 32; i++) cs += p[i * 256 + j];
    g_csp[(bz * 8 + rc) * 256 + j] = cs;
}

__global__ void pinv_scale_final()
{
    int bz = blockIdx.x, j = threadIdx.x;
    float cs = 0.f;
    #pragma unroll
    for (int rc = 0; rc < 8; rc++) cs += g_csp[(bz * 8 + rc) * 256 + j];
    atomicMax((int*)&g_scal[0], __float_as_int(cs));
}

// zinit via smem-tile transpose
__global__ void zinit_kernel()
{
    __shared__ float ts[32][33];
    int tr = blockIdx.x, tc = blockIdx.y, bz = blockIdx.z;
    const float* src = g_attn2 + ((long long)bz << 16);
    float* dst = g_z0 + ((long long)bz << 16);
    float inv = 1.f / g_scal[0];
    int lx = threadIdx.x & 31, ly = threadIdx.x >> 5;
    #pragma unroll
    for (int i = 0; i < 4; i++) {
        int c = tc * 32 + ly + i * 8;
        int r = tr * 32 + lx;
        ts[ly + i * 8][lx] = src[(c << 8) + r];
    }
    __syncthreads();
    #pragma unroll
    for (int i = 0; i < 4; i++) {
        int r = tr * 32 + ly + i * 8;
        int c = tc * 32 + lx;
        dst[(r << 8) + c] = tf32r(ts[lx][ly + i * 8] * inv);
    }
}

// ================= flash a3v v3: register-resident P (unchanged) ==========
__global__ void __launch_bounds__(256, 2) flash_a3v_tc_kernel()
{
    extern __shared__ float sm[];
    float* Qs   = sm;                 // [64][68]
    float* Ks   = sm + 4352;          // [128][68]
    float* Vs   = sm + 13056;         // [128][68]  (row-permuted; Os overlay at end)
    float* mred = sm + 21760;         // [2][64]
    float* sred = sm + 21888;         // [2][64]
    float* Os   = sm + 13056;         // overlay on Vs

    int ks   = blockIdx.x;
    int mt   = blockIdx.y;
    int bh   = blockIdx.z;
    int tid  = threadIdx.x;
    int warp = tid >> 5, lane = tid & 31;
    int gid  = lane >> 2, tig = lane & 3;
    int wm   = warp >> 1, wn = warp & 1;

    const float* qlb = g_ql + ((long long)bh * ML + mt * 64) * DH;
    for (int i = tid; i < 1024; i += 256) {
        int row = i >> 4, kq = (i & 15) << 2;
        *(float4*)&Qs[row * 68 + kq] = *(const float4*)&qlb[row * 64 + kq];
    }

    float sacc[8][4];
    float oacc[8][4] = {};
    float m0r = -1e30f, m1r = -1e30f, s0r = 0.f, s1r = 0.f;
    const int r0 = wm * 16 + gid, r1 = r0 + 8;

    const float* kb0 = g_k + (long long)bh * SEQ * DH;
    const float* vb0 = g_v + (long long)bh * SEQ * DH;
    int n_beg = ks * (SEQ / SPLIT);

    for (int nt = 0; nt < SEQ / SPLIT; nt += 128) {
        const float* kp = kb0 + (long long)(n_beg + nt) * DH;
        const float* vp = vb0 + (long long)(n_beg + nt) * DH;
        __syncthreads();
        for (int i = tid; i < 2048; i += 256) {
            int t = i >> 4, kq = (i & 15) << 2;
            cp16(&Ks[t * 68 + kq], &kp[t * 64 + kq]);
            int tsrc = (t & 0x78) | (((t & 3) << 1) | ((t >> 2) & 1));
            cp16(&Vs[t * 68 + kq], &vp[tsrc * 64 + kq]);
        }
        cp_commit();
        cp_wait0();
        __syncthreads();

        #pragma unroll
        for (int nf = 0; nf < 8; nf++) {
            sacc[nf][0] = 0.f; sacc[nf][1] = 0.f; sacc[nf][2] = 0.f; sacc[nf][3] = 0.f;
        }
        #pragma unroll
        for (int s = 0; s < 8; s++) {
            const int kb = s * 8;
            unsigned af[4];
            af[0] = __float_as_uint(Qs[r0 * 68 + kb + tig]);
            af[1] = __float_as_uint(Qs[r1 * 68 + kb + tig]);
            af[2] = __float_as_uint(Qs[r0 * 68 + kb + tig + 4]);
            af[3] = __float_as_uint(Qs[r1 * 68 + kb + tig + 4]);
            #pragma unroll
            for (int nf = 0; nf < 8; nf++) {
                int n = wn * 64 + nf * 8 + gid;
                unsigned b0 = __float_as_uint(Ks[n * 68 + kb + tig]);
                unsigned b1 = __float_as_uint(Ks[n * 68 + kb + tig + 4]);
                mma8(sacc[nf], af, b0, b1);
            }
        }

        float mx0 = -1e30f, mx1 = -1e30f;
        #pragma unroll
        for (int nf = 0; nf < 8; nf++) {
            mx0 = fmaxf(mx0, fmaxf(sacc[nf][0], sacc[nf][1]));
            mx1 = fmaxf(mx1, fmaxf(sacc[nf][2], sacc[nf][3]));
        }
        mx0 = fmaxf(mx0, __shfl_xor_sync(0xffffffffu, mx0, 1));
        mx0 = fmaxf(mx0, __shfl_xor_sync(0xffffffffu, mx0, 2));
        mx1 = fmaxf(mx1, __shfl_xor_sync(0xffffffffu, mx1, 1));
        mx1 = fmaxf(mx1, __shfl_xor_sync(0xffffffffu, mx1, 2));
        if (tig == 0) { mred[wn * 64 + r0] = mx0; mred[wn * 64 + r1] = mx1; }
        __syncthreads();
        float mn0 = fmaxf(m0r, fmaxf(mred[r0], mred[64 + r0]));
        float mn1 = fmaxf(m1r, fmaxf(mred[r1], mred[64 + r1]));
        float f0 = __expf(m0r - mn0), f1 = __expf(m1r - mn1);
        float ps0 = 0.f, ps1 = 0.f;
        #pragma unroll
        for (int nf = 0; nf < 8; nf++) {
            float e0 = __expf(sacc[nf][0] - mn0);
            float e1 = __expf(sacc[nf][1] - mn0);
            float e2 = __expf(sacc[nf][2] - mn1);
            float e3 = __expf(sacc[nf][3] - mn1);
            ps0 += e0 + e1; ps1 += e2 + e3;
            sacc[nf][0] = tf32r(e0); sacc[nf][1] = tf32r(e1);
            sacc[nf][2] = tf32r(e2); sacc[nf][3] = tf32r(e3);
        }
        ps0 += __shfl_xor_sync(0xffffffffu, ps0, 1);
        ps0 += __shfl_xor_sync(0xffffffffu, ps0, 2);
        ps1 += __shfl_xor_sync(0xffffffffu, ps1, 1);
        ps1 += __shfl_xor_sync(0xffffffffu, ps1, 2);
        if (tig == 0) { sred[wn * 64 + r0] = ps0; sred[wn * 64 + r1] = ps1; }
        __syncthreads();
        s0r = s0r * f0 + sred[r0] + sred[64 + r0];
        s1r = s1r * f1 + sred[r1] + sred[64 + r1];
        m0r = mn0; m1r = mn1;

        #pragma unroll
        for (int nf = 0; nf < 8; nf++) {
            oacc[nf][0] *= f0; oacc[nf][1] *= f0;
            oacc[nf][2] *= f1; oacc[nf][3] *= f1;
        }
        #pragma unroll
        for (int kg = 0; kg < 8; kg++) {
            unsigned af[4];
            af[0] = __float_as_uint(sacc[kg][0]);
            af[1] = __float_as_uint(sacc[kg][2]);
            af[2] = __float_as_uint(sacc[kg][1]);
            af[3] = __float_as_uint(sacc[kg][3]);
            int trow = wn * 64 + kg * 8;
            #pragma unroll
            for (int nf = 0; nf < 8; nf++) {
                int n = nf * 8 + gid;
                unsigned b0 = __float_as_uint(Vs[(trow + tig) * 68 + n]);
                unsigned b1 = __float_as_uint(Vs[(trow + tig + 4) * 68 + n]);
                mma8(oacc[nf], af, b0, b1);
            }
        }
    }

    __syncthreads();
    if (wn == 0) {
        #pragma unroll
        for (int nf = 0; nf < 8; nf++) {
            int c = nf * 8 + tig * 2;
            Os[r0 * 68 + c]     = oacc[nf][0];
            Os[r0 * 68 + c + 1] = oacc[nf][1];
            Os[r1 * 68 + c]     = oacc[nf][2];
            Os[r1 * 68 + c + 1] = oacc[nf][3];
        }
    }
    __syncthreads();
    if (wn == 1) {
        float* po = g_part_o + (((long long)ks * BH + bh) * ML + mt * 64) * DH;
        #pragma unroll
        for (int nf = 0; nf < 8; nf++) {
            int c = nf * 8 + tig * 2;
            po[r0 * 64 + c]     = oacc[nf][0] + Os[r0 * 68 + c];
            po[r0 * 64 + c + 1] = oacc[nf][1] + Os[r0 * 68 + c + 1];
            po[r1 * 64 + c]     = oacc[nf][2] + Os[r1 * 68 + c];
            po[r1 * 64 + c + 1] = oacc[nf][3] + Os[r1 * 68 + c + 1];
        }
        if (tig == 0) {
            long long ro = ((long long)ks * BH + bh) * ML + mt * 64;
            g_part_m[ro + r0] = m0r; g_part_s[ro + r0] = s0r;
            g_part_m[ro + r1] = m1r; g_part_s[ro + r1] = s1r;
        }
    }
}

// ---------------- merge flash partials ----------------
__global__ void a3v_merge_kernel()
{
    long long idx = (long long)blockIdx.x * 256 + threadIdx.x;
    if (idx >= 524288LL) return;
    int dh = (int)(idx & 63);
    long long row = idx >> 6;
    float M = -1e30f;
    #pragma unroll
    for (int k = 0; k < SPLIT; k++) M = fmaxf(M, g_part_m[k * 8192 + row]);
    float num = 0.f, den = 0.f;
    #pragma unroll
    for (int k = 0; k < SPLIT; k++) {
        float w = __expf(g_part_m[k * 8192 + row] - M);
        num += g_part_o[(k * 8192 + row) * 64 + dh] * w;
        den += g_part_s[k * 8192 + row] * w;
    }
    g_a3v[idx] = num / den;
}

// ================= attn1 v3: register-resident P + fused conv (unchanged) =========
__global__ void __launch_bounds__(256, 2) attn1_out_tc_kernel(const float* __restrict__ convw)
{
    extern __shared__ float sm[];
    float* Qs   = sm;                 // [64][68]
    float* Ks   = sm + 4352;          // [128][68] kl tile (vt overlay after loop)
    float* Ws   = sm + 13056;         // [128][68] wm tile, permuted (Os overlay at end)
    float* mred = sm + 21760;         // [2][64]
    float* sred = sm + 21888;         // [2][64]
    float* wsh  = sm + 22016;         // [33]
    float* vt   = sm + 4352;          // overlay on Ks: [96][64]
    float* Os   = sm + 13056;         // overlay on Ws

    int st   = blockIdx.x;
    int bh   = blockIdx.y;
    int b    = bh >> 3, h = bh & 7;
    int tid  = threadIdx.x;
    int warp = tid >> 5, lane = tid & 31;
    int gid  = lane >> 2, tig = lane & 3;
    int wm   = warp >> 1, wn = warp & 1;

    const float* qb  = g_q  + ((long long)bh * SEQ + st * 64) * DH;
    const float* klb = g_kl + (long long)bh * ML * DH;
    const float* wmb = g_wm + (long long)bh * ML * DH;

    for (int i = tid; i < 1024; i += 256) {
        int row = i >> 4, kq = (i & 15) << 2;
        *(float4*)&Qs[row * 68 + kq] = *(const float4*)&qb[row * 64 + kq];
    }
    if (tid < KCONV) wsh[tid] = convw[h * KCONV + tid];

    float sacc[8][4];
    float oacc[8][4] = {};
    float m0r = -1e30f, m1r = -1e30f, s0r = 0.f, s1r = 0.f;
    const int r0 = wm * 16 + gid, r1 = r0 + 8;

    for (int lt = 0; lt < 2; lt++) {
        const float* kp = klb + lt * 128 * DH;
        const float* wp = wmb + lt * 128 * DH;
        __syncthreads();
        for (int i = tid; i < 2048; i += 256) {
            int t = i >> 4, kq = (i & 15) << 2;
            cp16(&Ks[t * 68 + kq], &kp[t * 64 + kq]);
            int tsrc = (t & 0x78) | (((t & 3) << 1) | ((t >> 2) & 1));
            cp16(&Ws[t * 68 + kq], &wp[tsrc * 64 + kq]);
        }
        cp_commit();
        cp_wait0();
        __syncthreads();

        #pragma unroll
        for (int nf = 0; nf < 8; nf++) {
            sacc[nf][0] = 0.f; sacc[nf][1] = 0.f; sacc[nf][2] = 0.f; sacc[nf][3] = 0.f;
        }
        #pragma unroll
        for (int s = 0; s < 8; s++) {
            const int kb = s * 8;
            unsigned af[4];
            af[0] = __float_as_uint(Qs[r0 * 68 + kb + tig]);
            af[1] = __float_as_uint(Qs[r1 * 68 + kb + tig]);
            af[2] = __float_as_uint(Qs[r0 * 68 + kb + tig + 4]);
            af[3] = __float_as_uint(Qs[r1 * 68 + kb + tig + 4]);
            #pragma unroll
            for (int nf = 0; nf < 8; nf++) {
                int n = wn * 64 + nf * 8 + gid;
                unsigned b0 = __float_as_uint(Ks[n * 68 + kb + tig]);
                unsigned b1 = __float_as_uint(Ks[n * 68 + kb + tig + 4]);
                mma8(sacc[nf], af, b0, b1);
            }
        }

        float mx0 = -1e30f, mx1 = -1e30f;
        #pragma unroll
        for (int nf = 0; nf < 8; nf++) {
            mx0 = fmaxf(mx0, fmaxf(sacc[nf][0], sacc[nf][1]));
            mx1 = fmaxf(mx1, fmaxf(sacc[nf][2], sacc[nf][3]));
        }
        mx0 = fmaxf(mx0, __shfl_xor_sync(0xffffffffu, mx0, 1));
        mx0 = fmaxf(mx0, __shfl_xor_sync(0xffffffffu, mx0, 2));
        mx1 = fmaxf(mx1, __shfl_xor_sync(0xffffffffu, mx1, 1));
        mx1 = fmaxf(mx1, __shfl_xor_sync(0xffffffffu, mx1, 2));
        if (tig == 0) { mred[wn * 64 + r0] = mx0; mred[wn * 64 + r1] = mx1; }
        __syncthreads();
        float mn0 = fmaxf(m0r, fmaxf(mred[r0], mred[64 + r0]));
        float mn1 = fmaxf(m1r, fmaxf(mred[r1], mred[64 + r1]));
        float f0 = __expf(m0r - mn0), f1 = __expf(m1r - mn1);
        float ps0 = 0.f, ps1 = 0.f;
        #pragma unroll
        for (int nf = 0; nf < 8; nf++) {
            float e0 = __expf(sacc[nf][0] - mn0);
            float e1 = __expf(sacc[nf][1] - mn0);
            float e2 = __expf(sacc[nf][2] - mn1);
            float e3 = __expf(sacc[nf][3] - mn1);
            ps0 += e0 + e1; ps1 += e2 + e3;
            sacc[nf][0] = tf32r(e0); sacc[nf][1] = tf32r(e1);
            sacc[nf][2] = tf32r(e2); sacc[nf][3] = tf32r(e3);
        }
        ps0 += __shfl_xor_sync(0xffffffffu, ps0, 1);
        ps0 += __shfl_xor_sync(0xffffffffu, ps0, 2);
        ps1 += __shfl_xor_sync(0xffffffffu, ps1, 1);
        ps1 += __shfl_xor_sync(0xffffffffu, ps1, 2);
        if (tig == 0) { sred[wn * 64 + r0] = ps0; sred[wn * 64 + r1] = ps1; }
        __syncthreads();
        s0r = s0r * f0 + sred[r0] + sred[64 + r0];
        s1r = s1r * f1 + sred[r1] + sred[64 + r1];
        m0r = mn0; m1r = mn1;

        #pragma unroll
        for (int nf = 0; nf < 8; nf++) {
            oacc[nf][0] *= f0; oacc[nf][1] *= f0;
            oacc[nf][2] *= f1; oacc[nf][3] *= f1;
        }
        #pragma unroll
        for (int kg = 0; kg < 8; kg++) {
            unsigned af[4];
            af[0] = __float_as_uint(sacc[kg][0]);
            af[1] = __float_as_uint(sacc[kg][2]);
            af[2] = __float_as_uint(sacc[kg][1]);
            af[3] = __float_as_uint(sacc[kg][3]);
            int trow = wn * 64 + kg * 8;
            #pragma unroll
            for (int nf = 0; nf < 8; nf++) {
                int n = nf * 8 + gid;
                unsigned b0 = __float_as_uint(Ws[(trow + tig) * 68 + n]);
                unsigned b1 = __float_as_uint(Ws[(trow + tig + 4) * 68 + n]);
                mma8(oacc[nf], af, b0, b1);
            }
        }
    }

    __syncthreads();
    if (wn == 0) {
        #pragma unroll
        for (int nf = 0; nf < 8; nf++) {
            int c = nf * 8 + tig * 2;
            Os[r0 * 68 + c]     = oacc[nf][0];
            Os[r0 * 68 + c + 1] = oacc[nf][1];
            Os[r1 * 68 + c]     = oacc[nf][2];
            Os[r1 * 68 + c + 1] = oacc[nf][3];
        }
    }
    {
        const float* vbase = g_v + (long long)bh * SEQ * DH;
        int n0 = st * 64;
        for (int i = tid; i < 96 * 64; i += 256) {
            int r = i >> 6, dh = i & 63;
            int n = n0 + r - 16;
            vt[i] = (n >= 0 && n < SEQ) ? vbase[(long long)n * DH + dh] : 0.f;
        }
    }
    __syncthreads();
    if (wn == 1) {
        float inv0 = 1.f / s0r, inv1 = 1.f / s1r;
        float* yb = g_y + (((long long)b * SEQ + st * 64) * NDIM) + h * DH;
        #pragma unroll
        for (int nf = 0; nf < 8; nf++) {
            int c = nf * 8 + tig * 2;
            float o00 = (oacc[nf][0] + Os[r0 * 68 + c])     * inv0;
            float o01 = (oacc[nf][1] + Os[r0 * 68 + c + 1]) * inv0;
            float o10 = (oacc[nf][2] + Os[r1 * 68 + c])     * inv1;
            float o11 = (oacc[nf][3] + Os[r1 * 68 + c + 1]) * inv1;
            float c00 = 0.f, c01 = 0.f, c10 = 0.f, c11 = 0.f;
            #pragma unroll
            for (int t = 0; t < KCONV; t++) {
                float w = wsh[t];
                c00 = fmaf(w, vt[(r0 + t) * 64 + c], c00);
                c01 = fmaf(w, vt[(r0 + t) * 64 + c + 1], c01);
                c10 = fmaf(w, vt[(r1 + t) * 64 + c], c10);
                c11 = fmaf(w, vt[(r1 + t) * 64 + c + 1], c11);
            }
            yb[(long long)r0 * NDIM + c]     = tf32r(o00 + c00);
            yb[(long long)r0 * NDIM + c + 1] = tf32r(o01 + c01);
            yb[(long long)r1 * NDIM + c]     = tf32r(o10 + c10);
            yb[(long long)r1 * NDIM + c + 1] = tf32r(o11 + c11);
        }
    }
}

// ---------------- host orchestration ----------------
static float* sym(const void* p) { void* a = nullptr; cudaGetSymbolAddress(&a, p); return (float*)a; }

extern "C" void kernel_launch(void* const* d_in, const int* in_sizes, int n_in,
                              void* d_out, int out_size)
{
    const float* x      = (const float*)d_in[0];
    const float* w_qkv  = (const float*)d_in[1];
    const float* w_out  = (const float*)d_in[2];
    const float* b_out  = (const float*)d_in[3];
    const float* conv_w = (const float*)d_in[4];
    float* out = (float*)d_out;

    float* p_y  = sym(g_y);
    float* p_t  = sym(g_t);
    float* p_wo = sym(g_wout);

    static int attr_done = 0;
    if (!attr_done) {
        cudaFuncSetAttribute(attn2_fused_kernel,  cudaFuncAttributeMaxDynamicSharedMemorySize, 103000);
        cudaFuncSetAttribute(flash_a3v_tc_kernel, cudaFuncAttributeMaxDynamicSharedMemorySize, 88100);
        cudaFuncSetAttribute(attn1_out_tc_kernel, cudaFuncAttributeMaxDynamicSharedMemorySize, 88300);
        cudaFuncSetAttribute(tgemm_kernel<0>,     cudaFuncAttributeMaxDynamicSharedMemorySize, 74000);
        cudaFuncSetAttribute(tgemm_kernel<2>,     cudaFuncAttributeMaxDynamicSharedMemorySize, 74000);
        cudaFuncSetAttribute(pinv_fused_kernel,   cudaFuncAttributeMaxDynamicSharedMemorySize, 72000);
        attr_done = 1;
    }
    size_t a2_smem = (4352 + 4352 + 16640 + 64) * sizeof(float);
    size_t fl_smem = (4352 + 8704 + 8704 + 256) * sizeof(float);          // 88,064
    size_t a1_smem = (4352 + 8704 + 8704 + 256 + 33 + 3) * sizeof(float); // 88,208
    size_t tg_smem = 4 * ASTG * sizeof(float);                            // 73,728
    size_t pv_smem = 2 * (ASTG + BSTG) * sizeof(float);                   // 71,680

    // 0. pre-round external inputs (x -> g_y; w_qkv^T -> g_t; w_out^T -> g_wout)
    round_kernel<<<16384, 256>>>(p_y, x, 4194304);
    round_tr_kernel<<<dim3(48, 16), 256>>>(p_t, w_qkv, 512, 1536);
    round_tr_kernel<<<dim3(16, 16), 256>>>(p_wo, w_out, 512, 512);

    // 1. QKV projection (B = w_qkv^T, ldmatrix fragments)
    tgemm_kernel<2><<<dim3(12, 256, 1), 256, tg_smem>>>(
        p_y, p_t, nullptr, 512, 512, 512, 0, 1.f, nullptr, nullptr);

    // 2. landmark pooling
    pool_kernel<<<2048, 256>>>();

    // 3. attn2 = softmax(ql @ kl^T)
    attn2_fused_kernel<<<dim3(4, BH), 256, a2_smem>>>();

    // 4. pinv init
    pinv_scale_part<<<dim3(32, 8), 256>>>();
    pinv_scale_final<<<32, 256>>>();
    zinit_kernel<<<dim3(8, 8, 32), 256>>>();

    // 5. Newton-Schulz (fused; 128 blocks @ 512 threads, guaranteed co-resident)
    pinv_fused_kernel<<<PINV_BLOCKS, 512, pv_smem>>>();

    // 6. a3v = softmax(ql @ k^T) @ v   (register-P flash)
    flash_a3v_tc_kernel<<<dim3(SPLIT, 4, BH), 256, fl_smem>>>();
    a3v_merge_kernel<<<2048, 256>>>();

    // 7. wm = z @ a3v
    gemm_wm_kernel<<<dim3(1, 4, BH), 256>>>();

    // 8. y = softmax(q @ kl^T) @ wm + conv(v)   (register-P attn1)
    attn1_out_tc_kernel<<<dim3(128, BH), 256, a1_smem>>>(conv_w);

    // 9. out = y @ w_out + b_out + x   (B = w_out^T)
    tgemm_kernel<0><<<dim3(4, 256, 1), 256, tg_smem>>>(
        p_y, p_wo, out, 512, 512, 512, 512, 1.f, b_out, x);
}

// round 17
// speedup vs baseline: 1.0138x; 1.0138x over previous
#include <cuda_runtime.h>

// ---------------- problem constants ----------------
#define BATCH 4
#define SEQ   8192
#define NDIM  512
#define HEADS 8
#define DH    64
#define ML    256
#define LP    32
#define BH    32
#define MTOK  32768
#define KCONV 33
#define SPLIT 8
#define PINV_BLOCKS 128

// ---------------- scratch ----------------
__device__ float g_q[16777216];      // [BH, SEQ, DH]  tf32-rounded (q pre-scaled)
__device__ float g_k[16777216];      // tf32-rounded
__device__ float g_v[16777216];      // tf32-rounded
__device__ float g_ql[524288];       // tf32-rounded
__device__ float g_kl[524288];       // tf32-rounded
__device__ float g_attn2[2097152];   // rounded attn2
__device__ float g_z0[2097152];
__device__ float g_z1[2097152];
__device__ float g_xz[2097152];
__device__ float g_t[2097152];       // (step0: rounded w_qkv^T [1536][512]) then pinv scratch
__device__ float g_u[2097152];
__device__ float g_a3v[524288];
__device__ float g_wm[524288];       // tf32-rounded
__device__ float g_y[16777216];      // y (rounded), written by attn1
__device__ float g_wout[262144];     // rounded w_out^T [512][512]
__device__ float g_part_o[4194304];
__device__ float g_part_m[65536];
__device__ float g_part_s[65536];
__device__ float g_csp[65536];       // [bh*4+mt][256] column partial sums (from attn2)
__device__ float g_scal[2] = {0.f, 0.f};
__device__ unsigned g_cnt[BH];
__device__ volatile unsigned g_gen[BH];

// ================= helpers =================
__device__ __forceinline__ float tf32r(float f)
{
    unsigned u;
    asm("cvt.rna.tf32.f32 %0, %1;" : "=r"(u) : "f"(f));
    return __uint_as_float(u);
}
__device__ __forceinline__ float4 tf32r4(float4 v)
{
    float4 w;
    w.x = tf32r(v.x); w.y = tf32r(v.y); w.z = tf32r(v.z); w.w = tf32r(v.w);
    return w;
}

__device__ __forceinline__ void cp16(void* s, const void* g)
{
    unsigned sa = (unsigned)__cvta_generic_to_shared(s);
    asm volatile("cp.async.cg.shared.global [%0], [%1], 16;" :: "r"(sa), "l"(g));
}
__device__ __forceinline__ void cp_commit() { asm volatile("cp.async.commit_group;"); }
__device__ __forceinline__ void cp_wait0()  { asm volatile("cp.async.wait_group 0;"); }

__device__ __forceinline__ void mma8(float* c, const unsigned* a, unsigned b0, unsigned b1)
{
    asm volatile("mma.sync.aligned.m16n8k8.row.col.f32.tf32.tf32.f32 "
                 "{%0,%1,%2,%3},{%4,%5,%6,%7},{%8,%9},{%0,%1,%2,%3};"
                 : "+f"(c[0]), "+f"(c[1]), "+f"(c[2]), "+f"(c[3])
                 : "r"(a[0]), "r"(a[1]), "r"(a[2]), "r"(a[3]), "r"(b0), "r"(b1));
}

__device__ __forceinline__ void ldsm4(unsigned* r, unsigned saddr)
{
    asm volatile("ldmatrix.sync.aligned.m8n8.x4.shared.b16 {%0,%1,%2,%3}, [%4];"
                 : "=r"(r[0]), "=r"(r[1]), "=r"(r[2]), "=r"(r[3]) : "r"(saddr));
}

// per-batch 4-block barrier (proven deadlock-free: 128 blocks <= 148 SMs at 1/SM)
__device__ __forceinline__ void group_sync(int bz)
{
    __syncthreads();
    __threadfence();
    if (threadIdx.x == 0) {
        unsigned gen = g_gen[bz];
        if (atomicAdd(&g_cnt[bz], 1u) == 3u) {
            atomicExch(&g_cnt[bz], 0u);
            __threadfence();
            g_gen[bz] = gen + 1;
        } else {
            while (g_gen[bz] == gen) __nanosleep(32);
        }
    }
    __syncthreads();
}

// ---------------- tf32 transpose+round prelude ----------------
// dst[Cc][R] = tf32r(src[R][Cc]) via 32x32 smem tiles; grid (Cc/32, R/32)
__global__ void round_tr_kernel(float* __restrict__ dst, const float* __restrict__ src, int R, int Cc)
{
    __shared__ float ts[32][33];
    int c0 = blockIdx.x * 32, r0 = blockIdx.y * 32;
    int lx = threadIdx.x & 31, ly = threadIdx.x >> 5;
    #pragma unroll
    for (int i = 0; i < 4; i++)
        ts[ly + i * 8][lx] = src[(long long)(r0 + ly + i * 8) * Cc + c0 + lx];
    __syncthreads();
    #pragma unroll
    for (int i = 0; i < 4; i++)
        dst[(long long)(c0 + ly + i * 8) * R + r0 + lx] = tf32r(ts[lx][ly + i * 8]);
}

// ================= TF32 GEMM: k32, 2-stage, ldmatrix fragments, B TRANSPOSED ======
// CVTA: RNA-round A fragments in registers (A raw fp32 in gmem). B always pre-rounded.
#define ASTG 4608   // 128*36
template<int EPI, bool CVTA>
__global__ void __launch_bounds__(256, 2) tgemm_kernel(
    const float* __restrict__ A, const float* __restrict__ BT,
    float* __restrict__ C,
    int K, int lda, int ldb, int ldc,
    float alpha,
    const float* __restrict__ bias, const float* __restrict__ resid)
{
    extern __shared__ float smem[];
    float* As = smem;
    float* Bs = smem + 2 * ASTG;

    const int m0 = blockIdx.y * 128;
    const int n0 = blockIdx.x * 128;
    const int tid = threadIdx.x;
    const int warp = tid >> 5, lane = tid & 31;
    const int gid = lane >> 2, tig = lane & 3;
    const int wm = warp >> 1, wn = warp & 1;

    auto stage = [&](int s, int kk) {
        float* Ab = As + s * ASTG;
        float* Bb = Bs + s * ASTG;
        #pragma unroll
        for (int i = 0; i < 4; i++) {
            int slot = tid + i * 256;
            int r = slot >> 3, kq = (slot & 7) << 2;
            cp16(&Ab[r * 36 + kq], &A[(long long)(m0 + r) * lda + kk + kq]);
            cp16(&Bb[r * 36 + kq], &BT[(long long)(n0 + r) * ldb + kk + kq]);
        }
    };

    float acc[2][8][4] = {};

    stage(0, 0);
    cp_commit();

    const unsigned sAb = (unsigned)__cvta_generic_to_shared(As);
    const unsigned sBb = (unsigned)__cvta_generic_to_shared(Bs);
    const unsigned aoff = (((wm * 32 + (lane & 15)) * 36) + ((lane >> 4) << 2)) * 4u;
    const int brow = (lane & 7) + ((lane >> 4) << 3);
    const unsigned boff = (((wn * 64 + brow) * 36) + (((lane >> 3) & 1) << 2)) * 4u;

    int buf = 0;
    for (int k0 = 0; k0 < K; k0 += 32) {
        cp_wait0();
        __syncthreads();
        if (k0 + 32 < K) { stage(buf ^ 1, k0 + 32); cp_commit(); }

        unsigned ab = sAb + (unsigned)(buf * ASTG * 4);
        unsigned bb = sBb + (unsigned)(buf * ASTG * 4);
        #pragma unroll
        for (int s = 0; s < 4; s++) {
            const unsigned kb4 = s * 32;
            unsigned af[2][4], bf[8][2];
            ldsm4(af[0], ab + aoff + kb4);
            ldsm4(af[1], ab + aoff + 16u * 36u * 4u + kb4);
            if (CVTA) {
                #pragma unroll
                for (int mf = 0; mf < 2; mf++)
                    #pragma unroll
                    for (int i = 0; i < 4; i++)
                        af[mf][i] = __float_as_uint(tf32r(__uint_as_float(af[mf][i])));
            }
            #pragma unroll
            for (int np = 0; np < 4; np++) {
                unsigned t[4];
                ldsm4(t, bb + boff + (unsigned)(np * 16 * 36 * 4) + kb4);
                bf[np * 2][0]     = t[0];
                bf[np * 2][1]     = t[1];
                bf[np * 2 + 1][0] = t[2];
                bf[np * 2 + 1][1] = t[3];
            }
            #pragma unroll
            for (int mf = 0; mf < 2; mf++)
                #pragma unroll
                for (int nf = 0; nf < 8; nf++)
                    mma8(acc[mf][nf], af[mf], bf[nf][0], bf[nf][1]);
        }
        buf ^= 1;
    }

    #pragma unroll
    for (int mf = 0; mf < 2; mf++) {
        #pragma unroll
        for (int nf = 0; nf < 8; nf++) {
            int r0 = m0 + wm * 32 + mf * 16 + gid;
            int c0 = n0 + wn * 64 + nf * 8 + tig * 2;
            float v00 = alpha * acc[mf][nf][0];
            float v01 = alpha * acc[mf][nf][1];
            float v10 = alpha * acc[mf][nf][2];
            float v11 = alpha * acc[mf][nf][3];

            if (EPI == 0) {
                long long o0 = (long long)r0 * ldc + c0;
                long long o1 = (long long)(r0 + 8) * ldc + c0;
                if (bias)  { v00 += bias[c0]; v01 += bias[c0 + 1]; v10 += bias[c0]; v11 += bias[c0 + 1]; }
                if (resid) { v00 += resid[o0]; v01 += resid[o0 + 1]; v10 += resid[o1]; v11 += resid[o1 + 1]; }
                C[o0] = v00; C[o0 + 1] = v01;
                C[o1] = v10; C[o1 + 1] = v11;
            } else {
                int sec = c0 >> 9;
                int rem = c0 & 511;
                int h = rem >> 6, dh = rem & 63;
                #pragma unroll
                for (int rr = 0; rr < 2; rr++) {
                    int gm = r0 + rr * 8;
                    int b = gm >> 13, n = gm & 8191;
                    long long off = (((long long)(b * HEADS + h)) * SEQ + n) * DH + dh;
                    float a0 = rr ? v10 : v00;
                    float a1 = rr ? v11 : v01;
                    if (sec == 0)      { g_q[off] = tf32r(a0 * 0.125f); g_q[off + 1] = tf32r(a1 * 0.125f); }
                    else if (sec == 1) { g_k[off] = tf32r(a0);          g_k[off + 1] = tf32r(a1); }
                    else               { g_v[off] = tf32r(a0);          g_v[off + 1] = tf32r(a1); }
                }
            }
        }
    }
}

// ================= fused Newton-Schulz pinv (R14 config: 256 thr, A via ldmatrix) ==
#define BSTG 4352   // 32*136
__device__ __forceinline__ void gemm_tile256(
    float* As, float* Bs,
    const float* __restrict__ A, const float* __restrict__ B,
    float* __restrict__ C, float* __restrict__ D,
    float alpha, float diag, int m0, int n0)
{
    const int tid = threadIdx.x;
    const int warp = tid >> 5, lane = tid & 31;
    const int gid = lane >> 2, tig = lane & 3;
    const int wm = warp >> 1, wn = warp & 1;

    auto stage = [&](int s, int kk) {
        float* Ab = As + s * ASTG;
        float* Bb = Bs + s * BSTG;
        #pragma unroll
        for (int i = 0; i < 4; i++) {
            int slot = tid + i * 256;
            int ar = slot >> 3, akq = (slot & 7) << 2;
            cp16(&Ab[ar * 36 + akq], &A[(m0 + ar) * 256 + kk + akq]);
            int br = slot >> 5, bnq = (slot & 31) << 2;
            cp16(&Bb[br * 136 + bnq], &B[(kk + br) * 256 + n0 + bnq]);
        }
    };

    float acc[2][8][4] = {};

    stage(0, 0);
    cp_commit();

    const unsigned sAb = (unsigned)__cvta_generic_to_shared(As);
    const unsigned aoff = (((wm * 32 + (lane & 15)) * 36) + ((lane >> 4) << 2)) * 4u;

    int buf = 0;
    for (int k0 = 0; k0 < 256; k0 += 32) {
        cp_wait0();
        __syncthreads();
        if (k0 + 32 < 256) { stage(buf ^ 1, k0 + 32); cp_commit(); }

        unsigned ab = sAb + (unsigned)(buf * ASTG * 4);
        float* Bb = Bs + buf * BSTG;
        #pragma unroll
        for (int s = 0; s < 4; s++) {
            const int kb = s * 8;
            unsigned af[2][4], bf[8][2];
            ldsm4(af[0], ab + aoff + (unsigned)(kb * 4));
            ldsm4(af[1], ab + aoff + 16u * 36u * 4u + (unsigned)(kb * 4));
            #pragma unroll
            for (int nf = 0; nf < 8; nf++) {
                int c = wn * 64 + nf * 8 + gid;
                bf[nf][0] = __float_as_uint(Bb[(kb + tig) * 136 + c]);
                bf[nf][1] = __float_as_uint(Bb[(kb + tig + 4) * 136 + c]);
            }
            #pragma unroll
            for (int mf = 0; mf < 2; mf++)
                #pragma unroll
                for (int nf = 0; nf < 8; nf++)
                    mma8(acc[mf][nf], af[mf], bf[nf][0], bf[nf][1]);
        }
        buf ^= 1;
    }

    #pragma unroll
    for (int mf = 0; mf < 2; mf++)
        #pragma unroll
        for (int nf = 0; nf < 8; nf++) {
            int r0 = m0 + wm * 32 + mf * 16 + gid;
            int c0 = n0 + wn * 64 + nf * 8 + tig * 2;
            float v00 = alpha * acc[mf][nf][0];
            float v01 = alpha * acc[mf][nf][1];
            float v10 = alpha * acc[mf][nf][2];
            float v11 = alpha * acc[mf][nf][3];
            int o0 = r0 * 256 + c0;
            int o1 = (r0 + 8) * 256 + c0;
            if (C) {
                C[o0] = tf32r(v00); C[o0 + 1] = tf32r(v01);
                C[o1] = tf32r(v10); C[o1 + 1] = tf32r(v11);
            }
            if (D) {
                D[o0]     = tf32r((r0 == c0         ? diag : 0.f) - v00);
                D[o0 + 1] = tf32r((r0 == c0 + 1     ? diag : 0.f) - v01);
                D[o1]     = tf32r((r0 + 8 == c0     ? diag : 0.f) - v10);
                D[o1 + 1] = tf32r((r0 + 8 == c0 + 1 ? diag : 0.f) - v11);
            }
        }
}

__global__ void __launch_bounds__(256, 1) pinv_fused_kernel()
{
    extern __shared__ float smem[];
    float* As = smem;
    float* Bs = smem + 2 * ASTG;

    const int bx = blockIdx.x;
    const int bz = bx >> 2;
    const int m0 = ((bx >> 1) & 1) * 128;
    const int n0 = (bx & 1) * 128;

    float* a2 = g_attn2 + bz * 65536;
    float* xz = g_xz + bz * 65536;
    float* tt = g_t  + bz * 65536;
    float* uu = g_u  + bz * 65536;
    float* zc = g_z0 + bz * 65536;
    float* zn = g_z1 + bz * 65536;

    for (int it = 0; it < 6; it++) {
        gemm_tile256(As, Bs, a2, zc, xz, tt, 1.f, 7.f, m0, n0);
        group_sync(bz);
        gemm_tile256(As, Bs, xz, tt, nullptr, uu, 1.f, 15.f, m0, n0);
        group_sync(bz);
        gemm_tile256(As, Bs, xz, uu, nullptr, tt, 1.f, 13.f, m0, n0);
        group_sync(bz);
        gemm_tile256(As, Bs, zc, tt, zn, nullptr, 0.25f, 0.f, m0, n0);
        group_sync(bz);
        float* tmp = zc; zc = zn; zn = tmp;
    }
}

// ---------------- small SIMT GEMM: wm = z @ a3v ----------------
__global__ void gemm_wm_kernel()
{
    int bz = blockIdx.z;
    const float* A = g_z0 + (long long)bz * 65536;
    const float* B = g_a3v + (long long)bz * ML * DH;
    float* C = g_wm + (long long)bz * ML * DH;

    __shared__ float As[16][68];
    __shared__ float Bs[16][68];

    const int tid = threadIdx.x;
    const int tx = tid & 15, ty = tid >> 4;
    const int m0 = blockIdx.y * 64;

    float acc[4][4] = {};
    for (int k0 = 0; k0 < ML; k0 += 16) {
        #pragma unroll
        for (int i = tid; i < 1024; i += 256) {
            int m = i >> 4, kk = i & 15;
            As[kk][m] = A[(m0 + m) * ML + k0 + kk];
        }
        #pragma unroll
        for (int i = tid; i < 1024; i += 256) {
            int kk = i >> 6, n = i & 63;
            Bs[kk][n] = B[(k0 + kk) * DH + n];
        }
        __syncthreads();
        #pragma unroll
        for (int kk = 0; kk < 16; kk++) {
            float a[4], bb[4];
            #pragma unroll
            for (int i = 0; i < 4; i++) a[i] = As[kk][ty * 4 + i];
            #pragma unroll
            for (int j = 0; j < 4; j++) bb[j] = Bs[kk][tx * 4 + j];
            #pragma unroll
            for (int i = 0; i < 4; i++)
                #pragma unroll
                for (int j = 0; j < 4; j++)
                    acc[i][j] = fmaf(a[i], bb[j], acc[i][j]);
        }
        __syncthreads();
    }
    #pragma unroll
    for (int i = 0; i < 4; i++)
        #pragma unroll
        for (int j = 0; j < 4; j++)
            C[(m0 + ty * 4 + i) * DH + tx * 4 + j] = tf32r(acc[i][j]);
}

// ---------------- landmark mean pooling ----------------
__global__ void pool_kernel()
{
    long long idx = (long long)blockIdx.x * 256 + threadIdx.x;
    if (idx >= 524288LL) return;
    int dh = idx & 63;
    int mi = (int)((idx >> 6) & 255);
    int bh = (int)(idx >> 14);
    const float* q = g_q + ((long long)bh * SEQ + mi * LP) * DH + dh;
    const float* k = g_k + ((long long)bh * SEQ + mi * LP) * DH + dh;
    float sq = 0.f, sk = 0.f;
    #pragma unroll
    for (int j = 0; j < LP; j++) { sq += q[j * DH]; sk += k[j * DH]; }
    g_ql[idx] = tf32r(sq * (1.f / LP));
    g_kl[idx] = tf32r(sk * (1.f / LP));
}

// ---------------- fused attn2 = softmax(ql @ kl^T) + column partial sums ----------
__global__ void attn2_fused_kernel()
{
    extern __shared__ float sm[];
    float* QsT = sm;
    float* Bt  = sm + 4352;
    float* Lg  = sm + 8704;
    float* inv = sm + 8704 + 16640;

    int mt = blockIdx.x;
    int bh = blockIdx.y;
    int tid = threadIdx.x;
    int tx = tid & 15, ty = tid >> 4;

    const float* qlb = g_ql + ((long long)bh * ML + mt * 64) * DH;
    const float* klb = g_kl + (long long)bh * ML * DH;

    for (int i = tid; i < 4096; i += 256) {
        int row = i >> 6, dh = i & 63;
        QsT[dh * 68 + row] = qlb[row * 64 + dh];
    }

    for (int lt = 0; lt < 4; lt++) {
        __syncthreads();
        for (int i = tid; i < 4096; i += 256) {
            int n = i >> 6, dh = i & 63;
            Bt[dh * 68 + n] = klb[(lt * 64 + n) * 64 + dh];
        }
        __syncthreads();
        float s2[4][4] = {};
        #pragma unroll
        for (int kk = 0; kk < 64; kk++) {
            float a[4], b[4];
            #pragma unroll
            for (int i = 0; i < 4; i++) a[i] = QsT[kk * 68 + ty * 4 + i];
            #pragma unroll
            for (int j = 0; j < 4; j++) b[j] = Bt[kk * 68 + tx * 4 + j];
            #pragma unroll
            for (int i = 0; i < 4; i++)
                #pragma unroll
                for (int j = 0; j < 4; j++)
                    s2[i][j] = fmaf(a[i], b[j], s2[i][j]);
        }
        #pragma unroll
        for (int i = 0; i < 4; i++)
            #pragma unroll
            for (int j = 0; j < 4; j++)
                Lg[(ty * 4 + i) * 260 + lt * 64 + tx * 4 + j] = s2[i][j];
    }
    __syncthreads();

    {
        int r = tid >> 2, c0 = (tid & 3) * 64;
        float mx = -1e30f;
        for (int c = 0; c < 64; c++) mx = fmaxf(mx, Lg[r * 260 + c0 + c]);
        mx = fmaxf(mx, __shfl_xor_sync(0xffffffffu, mx, 1));
        mx = fmaxf(mx, __shfl_xor_sync(0xffffffffu, mx, 2));
        float sum = 0.f;
        for (int c = 0; c < 64; c++) {
            float e = __expf(Lg[r * 260 + c0 + c] - mx);
            Lg[r * 260 + c0 + c] = e;
            sum += e;
        }
        sum += __shfl_xor_sync(0xffffffffu, sum, 1);
        sum += __shfl_xor_sync(0xffffffffu, sum, 2);
        if ((tid & 3) == 0) inv[r] = 1.f / sum;
    }
    __syncthreads();

    float* ob = g_attn2 + ((long long)bh * ML + mt * 64) * ML;
    for (int i = tid; i < 16384; i += 256) {
        int row = i >> 8, col = i & 255;
        ob[row * 256 + col] = tf32r(Lg[row * 260 + col] * inv[row]);
    }

    // column partial sums of the rounded tile (for pinv scale); thread = column
    {
        float cs = 0.f;
        #pragma unroll 8
        for (int r = 0; r < 64; r++)
            cs += tf32r(Lg[r * 260 + tid] * inv[r]);
        g_csp[(bh * 4 + mt) * 256 + tid] = cs;
    }
}

// ---------------- pinv scale (final reduce only; partials from attn2) -------------
__global__ void pinv_scale_final()
{
    int bz = blockIdx.x, j = threadIdx.x;
    float cs = 0.f;
    #pragma unroll
    for (int rc = 0; rc < 4; rc++) cs += g_csp[(bz * 4 + rc) * 256 + j];
    atomicMax((int*)&g_scal[0], __float_as_int(cs));
}

// zinit via smem-tile transpose
__global__ void zinit_kernel()
{
    __shared__ float ts[32][33];
    int tr = blockIdx.x, tc = blockIdx.y, bz = blockIdx.z;
    const float* src = g_attn2 + ((long long)bz << 16);
    float* dst = g_z0 + ((long long)bz << 16);
    float inv = 1.f / g_scal[0];
    int lx = threadIdx.x & 31, ly = threadIdx.x >> 5;
    #pragma unroll
    for (int i = 0; i < 4; i++) {
        int c = tc * 32 + ly + i * 8;
        int r = tr * 32 + lx;
        ts[ly + i * 8][lx] = src[(c << 8) + r];
    }
    __syncthreads();
    #pragma unroll
    for (int i = 0; i < 4; i++) {
        int r = tr * 32 + ly + i * 8;
        int c = tc * 32 + lx;
        dst[(r << 8) + c] = tf32r(ts[lx][ly + i * 8] * inv);
    }
}

// ================= flash a3v v3: register-resident P =================
__global__ void __launch_bounds__(256, 2) flash_a3v_tc_kernel()
{
    extern __shared__ float sm[];
    float* Qs   = sm;                 // [64][68]
    float* Ks   = sm + 4352;          // [128][68]
    float* Vs   = sm + 13056;         // [128][68]  (row-permuted; Os overlay at end)
    float* mred = sm + 21760;         // [2][64]
    float* sred = sm + 21888;         // [2][64]
    float* Os   = sm + 13056;         // overlay on Vs

    int ks   = blockIdx.x;
    int mt   = blockIdx.y;
    int bh   = blockIdx.z;
    int tid  = threadIdx.x;
    int warp = tid >> 5, lane = tid & 31;
    int gid  = lane >> 2, tig = lane & 3;
    int wm   = warp >> 1, wn = warp & 1;

    const float* qlb = g_ql + ((long long)bh * ML + mt * 64) * DH;
    for (int i = tid; i < 1024; i += 256) {
        int row = i >> 4, kq = (i & 15) << 2;
        *(float4*)&Qs[row * 68 + kq] = *(const float4*)&qlb[row * 64 + kq];
    }

    float sacc[8][4];
    float oacc[8][4] = {};
    float m0r = -1e30f, m1r = -1e30f, s0r = 0.f, s1r = 0.f;
    const int r0 = wm * 16 + gid, r1 = r0 + 8;

    const float* kb0 = g_k + (long long)bh * SEQ * DH;
    const float* vb0 = g_v + (long long)bh * SEQ * DH;
    int n_beg = ks * (SEQ / SPLIT);

    for (int nt = 0; nt < SEQ / SPLIT; nt += 128) {
        const float* kp = kb0 + (long long)(n_beg + nt) * DH;
        const float* vp = vb0 + (long long)(n_beg + nt) * DH;
        __syncthreads();
        for (int i = tid; i < 2048; i += 256) {
            int t = i >> 4, kq = (i & 15) << 2;
            cp16(&Ks[t * 68 + kq], &kp[t * 64 + kq]);
            int tsrc = (t & 0x78) | (((t & 3) << 1) | ((t >> 2) & 1));
            cp16(&Vs[t * 68 + kq], &vp[tsrc * 64 + kq]);
        }
        cp_commit();
        cp_wait0();
        __syncthreads();

        #pragma unroll
        for (int nf = 0; nf < 8; nf++) {
            sacc[nf][0] = 0.f; sacc[nf][1] = 0.f; sacc[nf][2] = 0.f; sacc[nf][3] = 0.f;
        }
        #pragma unroll
        for (int s = 0; s < 8; s++) {
            const int kb = s * 8;
            unsigned af[4];
            af[0] = __float_as_uint(Qs[r0 * 68 + kb + tig]);
            af[1] = __float_as_uint(Qs[r1 * 68 + kb + tig]);
            af[2] = __float_as_uint(Qs[r0 * 68 + kb + tig + 4]);
            af[3] = __float_as_uint(Qs[r1 * 68 + kb + tig + 4]);
            #pragma unroll
            for (int nf = 0; nf < 8; nf++) {
                int n = wn * 64 + nf * 8 + gid;
                unsigned b0 = __float_as_uint(Ks[n * 68 + kb + tig]);
                unsigned b1 = __float_as_uint(Ks[n * 68 + kb + tig + 4]);
                mma8(sacc[nf], af, b0, b1);
            }
        }

        float mx0 = -1e30f, mx1 = -1e30f;
        #pragma unroll
        for (int nf = 0; nf < 8; nf++) {
            mx0 = fmaxf(mx0, fmaxf(sacc[nf][0], sacc[nf][1]));
            mx1 = fmaxf(mx1, fmaxf(sacc[nf][2], sacc[nf][3]));
        }
        mx0 = fmaxf(mx0, __shfl_xor_sync(0xffffffffu, mx0, 1));
        mx0 = fmaxf(mx0, __shfl_xor_sync(0xffffffffu, mx0, 2));
        mx1 = fmaxf(mx1, __shfl_xor_sync(0xffffffffu, mx1, 1));
        mx1 = fmaxf(mx1, __shfl_xor_sync(0xffffffffu, mx1, 2));
        if (tig == 0) { mred[wn * 64 + r0] = mx0; mred[wn * 64 + r1] = mx1; }
        __syncthreads();
        float mn0 = fmaxf(m0r, fmaxf(mred[r0], mred[64 + r0]));
        float mn1 = fmaxf(m1r, fmaxf(mred[r1], mred[64 + r1]));
        float f0 = __expf(m0r - mn0), f1 = __expf(m1r - mn1);
        float ps0 = 0.f, ps1 = 0.f;
        #pragma unroll
        for (int nf = 0; nf < 8; nf++) {
            float e0 = __expf(sacc[nf][0] - mn0);
            float e1 = __expf(sacc[nf][1] - mn0);
            float e2 = __expf(sacc[nf][2] - mn1);
            float e3 = __expf(sacc[nf][3] - mn1);
            ps0 += e0 + e1; ps1 += e2 + e3;
            sacc[nf][0] = tf32r(e0); sacc[nf][1] = tf32r(e1);
            sacc[nf][2] = tf32r(e2); sacc[nf][3] = tf32r(e3);
        }
        ps0 += __shfl_xor_sync(0xffffffffu, ps0, 1);
        ps0 += __shfl_xor_sync(0xffffffffu, ps0, 2);
        ps1 += __shfl_xor_sync(0xffffffffu, ps1, 1);
        ps1 += __shfl_xor_sync(0xffffffffu, ps1, 2);
        if (tig == 0) { sred[wn * 64 + r0] = ps0; sred[wn * 64 + r1] = ps1; }
        __syncthreads();
        s0r = s0r * f0 + sred[r0] + sred[64 + r0];
        s1r = s1r * f1 + sred[r1] + sred[64 + r1];
        m0r = mn0; m1r = mn1;

        #pragma unroll
        for (int nf = 0; nf < 8; nf++) {
            oacc[nf][0] *= f0; oacc[nf][1] *= f0;
            oacc[nf][2] *= f1; oacc[nf][3] *= f1;
        }
        #pragma unroll
        for (int kg = 0; kg < 8; kg++) {
            unsigned af[4];
            af[0] = __float_as_uint(sacc[kg][0]);
            af[1] = __float_as_uint(sacc[kg][2]);
            af[2] = __float_as_uint(sacc[kg][1]);
            af[3] = __float_as_uint(sacc[kg][3]);
            int trow = wn * 64 + kg * 8;
            #pragma unroll
            for (int nf = 0; nf < 8; nf++) {
                int n = nf * 8 + gid;
                unsigned b0 = __float_as_uint(Vs[(trow + tig) * 68 + n]);
                unsigned b1 = __float_as_uint(Vs[(trow + tig + 4) * 68 + n]);
                mma8(oacc[nf], af, b0, b1);
            }
        }
    }

    __syncthreads();
    if (wn == 0) {
        #pragma unroll
        for (int nf = 0; nf < 8; nf++) {
            int c = nf * 8 + tig * 2;
            Os[r0 * 68 + c]     = oacc[nf][0];
            Os[r0 * 68 + c + 1] = oacc[nf][1];
            Os[r1 * 68 + c]     = oacc[nf][2];
            Os[r1 * 68 + c + 1] = oacc[nf][3];
        }
    }
    __syncthreads();
    if (wn == 1) {
        float* po = g_part_o + (((long long)ks * BH + bh) * ML + mt * 64) * DH;
        #pragma unroll
        for (int nf = 0; nf < 8; nf++) {
            int c = nf * 8 + tig * 2;
            po[r0 * 64 + c]     = oacc[nf][0] + Os[r0 * 68 + c];
            po[r0 * 64 + c + 1] = oacc[nf][1] + Os[r0 * 68 + c + 1];
            po[r1 * 64 + c]     = oacc[nf][2] + Os[r1 * 68 + c];
            po[r1 * 64 + c + 1] = oacc[nf][3] + Os[r1 * 68 + c + 1];
        }
        if (tig == 0) {
            long long ro = ((long long)ks * BH + bh) * ML + mt * 64;
            g_part_m[ro + r0] = m0r; g_part_s[ro + r0] = s0r;
            g_part_m[ro + r1] = m1r; g_part_s[ro + r1] = s1r;
        }
    }
}

// ---------------- merge flash partials ----------------
__global__ void a3v_merge_kernel()
{
    long long idx = (long long)blockIdx.x * 256 + threadIdx.x;
    if (idx >= 524288LL) return;
    int dh = (int)(idx & 63);
    long long row = idx >> 6;
    float M = -1e30f;
    #pragma unroll
    for (int k = 0; k < SPLIT; k++) M = fmaxf(M, g_part_m[k * 8192 + row]);
    float num = 0.f, den = 0.f;
    #pragma unroll
    for (int k = 0; k < SPLIT; k++) {
        float w = __expf(g_part_m[k * 8192 + row] - M);
        num += g_part_o[(k * 8192 + row) * 64 + dh] * w;
        den += g_part_s[k * 8192 + row] * w;
    }
    g_a3v[idx] = num / den;
}

// ================= attn1 v3: register-resident P + fused conv =================
__global__ void __launch_bounds__(256, 2) attn1_out_tc_kernel(const float* __restrict__ convw)
{
    extern __shared__ float sm[];
    float* Qs   = sm;                 // [64][68]
    float* Ks   = sm + 4352;          // [128][68] kl tile (vt overlay after loop)
    float* Ws   = sm + 13056;         // [128][68] wm tile, permuted (Os overlay at end)
    float* mred = sm + 21760;         // [2][64]
    float* sred = sm + 21888;         // [2][64]
    float* wsh  = sm + 22016;         // [33]
    float* vt   = sm + 4352;          // overlay on Ks: [96][64]
    float* Os   = sm + 13056;         // overlay on Ws

    int st   = blockIdx.x;
    int bh   = blockIdx.y;
    int b    = bh >> 3, h = bh & 7;
    int tid  = threadIdx.x;
    int warp = tid >> 5, lane = tid & 31;
    int gid  = lane >> 2, tig = lane & 3;
    int wm   = warp >> 1, wn = warp & 1;

    const float* qb  = g_q  + ((long long)bh * SEQ + st * 64) * DH;
    const float* klb = g_kl + (long long)bh * ML * DH;
    const float* wmb = g_wm + (long long)bh * ML * DH;

    for (int i = tid; i < 1024; i += 256) {
        int row = i >> 4, kq = (i & 15) << 2;
        *(float4*)&Qs[row * 68 + kq] = *(const float4*)&qb[row * 64 + kq];
    }
    if (tid < KCONV) wsh[tid] = convw[h * KCONV + tid];

    float sacc[8][4];
    float oacc[8][4] = {};
    float m0r = -1e30f, m1r = -1e30f, s0r = 0.f, s1r = 0.f;
    const int r0 = wm * 16 + gid, r1 = r0 + 8;

    for (int lt = 0; lt < 2; lt++) {
        const float* kp = klb + lt * 128 * DH;
        const float* wp = wmb + lt * 128 * DH;
        __syncthreads();
        for (int i = tid; i < 2048; i += 256) {
            int t = i >> 4, kq = (i & 15) << 2;
            cp16(&Ks[t * 68 + kq], &kp[t * 64 + kq]);
            int tsrc = (t & 0x78) | (((t & 3) << 1) | ((t >> 2) & 1));
            cp16(&Ws[t * 68 + kq], &wp[tsrc * 64 + kq]);
        }
        cp_commit();
        cp_wait0();
        __syncthreads();

        #pragma unroll
        for (int nf = 0; nf < 8; nf++) {
            sacc[nf][0] = 0.f; sacc[nf][1] = 0.f; sacc[nf][2] = 0.f; sacc[nf][3] = 0.f;
        }
        #pragma unroll
        for (int s = 0; s < 8; s++) {
            const int kb = s * 8;
            unsigned af[4];
            af[0] = __float_as_uint(Qs[r0 * 68 + kb + tig]);
            af[1] = __float_as_uint(Qs[r1 * 68 + kb + tig]);
            af[2] = __float_as_uint(Qs[r0 * 68 + kb + tig + 4]);
            af[3] = __float_as_uint(Qs[r1 * 68 + kb + tig + 4]);
            #pragma unroll
            for (int nf = 0; nf < 8; nf++) {
                int n = wn * 64 + nf * 8 + gid;
                unsigned b0 = __float_as_uint(Ks[n * 68 + kb + tig]);
                unsigned b1 = __float_as_uint(Ks[n * 68 + kb + tig + 4]);
                mma8(sacc[nf], af, b0, b1);
            }
        }

        float mx0 = -1e30f, mx1 = -1e30f;
        #pragma unroll
        for (int nf = 0; nf < 8; nf++) {
            mx0 = fmaxf(mx0, fmaxf(sacc[nf][0], sacc[nf][1]));
            mx1 = fmaxf(mx1, fmaxf(sacc[nf][2], sacc[nf][3]));
        }
        mx0 = fmaxf(mx0, __shfl_xor_sync(0xffffffffu, mx0, 1));
        mx0 = fmaxf(mx0, __shfl_xor_sync(0xffffffffu, mx0, 2));
        mx1 = fmaxf(mx1, __shfl_xor_sync(0xffffffffu, mx1, 1));
        mx1 = fmaxf(mx1, __shfl_xor_sync(0xffffffffu, mx1, 2));
        if (tig == 0) { mred[wn * 64 + r0] = mx0; mred[wn * 64 + r1] = mx1; }
        __syncthreads();
        float mn0 = fmaxf(m0r, fmaxf(mred[r0], mred[64 + r0]));
        float mn1 = fmaxf(m1r, fmaxf(mred[r1], mred[64 + r1]));
        float f0 = __expf(m0r - mn0), f1 = __expf(m1r - mn1);
        float ps0 = 0.f, ps1 = 0.f;
        #pragma unroll
        for (int nf = 0; nf < 8; nf++) {
            float e0 = __expf(sacc[nf][0] - mn0);
            float e1 = __expf(sacc[nf][1] - mn0);
            float e2 = __expf(sacc[nf][2] - mn1);
            float e3 = __expf(sacc[nf][3] - mn1);
            ps0 += e0 + e1; ps1 += e2 + e3;
            sacc[nf][0] = tf32r(e0); sacc[nf][1] = tf32r(e1);
            sacc[nf][2] = tf32r(e2); sacc[nf][3] = tf32r(e3);
        }
        ps0 += __shfl_xor_sync(0xffffffffu, ps0, 1);
        ps0 += __shfl_xor_sync(0xffffffffu, ps0, 2);
        ps1 += __shfl_xor_sync(0xffffffffu, ps1, 1);
        ps1 += __shfl_xor_sync(0xffffffffu, ps1, 2);
        if (tig == 0) { sred[wn * 64 + r0] = ps0; sred[wn * 64 + r1] = ps1; }
        __syncthreads();
        s0r = s0r * f0 + sred[r0] + sred[64 + r0];
        s1r = s1r * f1 + sred[r1] + sred[64 + r1];
        m0r = mn0; m1r = mn1;

        #pragma unroll
        for (int nf = 0; nf < 8; nf++) {
            oacc[nf][0] *= f0; oacc[nf][1] *= f0;
            oacc[nf][2] *= f1; oacc[nf][3] *= f1;
        }
        #pragma unroll
        for (int kg = 0; kg < 8; kg++) {
            unsigned af[4];
            af[0] = __float_as_uint(sacc[kg][0]);
            af[1] = __float_as_uint(sacc[kg][2]);
            af[2] = __float_as_uint(sacc[kg][1]);
            af[3] = __float_as_uint(sacc[kg][3]);
            int trow = wn * 64 + kg * 8;
            #pragma unroll
            for (int nf = 0; nf < 8; nf++) {
                int n = nf * 8 + gid;
                unsigned b0 = __float_as_uint(Ws[(trow + tig) * 68 + n]);
                unsigned b1 = __float_as_uint(Ws[(trow + tig + 4) * 68 + n]);
                mma8(oacc[nf], af, b0, b1);
            }
        }
    }

    __syncthreads();
    if (wn == 0) {
        #pragma unroll
        for (int nf = 0; nf < 8; nf++) {
            int c = nf * 8 + tig * 2;
            Os[r0 * 68 + c]     = oacc[nf][0];
            Os[r0 * 68 + c + 1] = oacc[nf][1];
            Os[r1 * 68 + c]     = oacc[nf][2];
            Os[r1 * 68 + c + 1] = oacc[nf][3];
        }
    }
    {
        const float* vbase = g_v + (long long)bh * SEQ * DH;
        int n0 = st * 64;
        for (int i = tid; i < 96 * 64; i += 256) {
            int r = i >> 6, dh = i & 63;
            int n = n0 + r - 16;
            vt[i] = (n >= 0 && n < SEQ) ? vbase[(long long)n * DH + dh] : 0.f;
        }
    }
    __syncthreads();
    if (wn == 1) {
        float inv0 = 1.f / s0r, inv1 = 1.f / s1r;
        float* yb = g_y + (((long long)b * SEQ + st * 64) * NDIM) + h * DH;
        #pragma unroll
        for (int nf = 0; nf < 8; nf++) {
            int c = nf * 8 + tig * 2;
            float o00 = (oacc[nf][0] + Os[r0 * 68 + c])     * inv0;
            float o01 = (oacc[nf][1] + Os[r0 * 68 + c + 1]) * inv0;
            float o10 = (oacc[nf][2] + Os[r1 * 68 + c])     * inv1;
            float o11 = (oacc[nf][3] + Os[r1 * 68 + c + 1]) * inv1;
            float c00 = 0.f, c01 = 0.f, c10 = 0.f, c11 = 0.f;
            #pragma unroll
            for (int t = 0; t < KCONV; t++) {
                float w = wsh[t];
                c00 = fmaf(w, vt[(r0 + t) * 64 + c], c00);
                c01 = fmaf(w, vt[(r0 + t) * 64 + c + 1], c01);
                c10 = fmaf(w, vt[(r1 + t) * 64 + c], c10);
                c11 = fmaf(w, vt[(r1 + t) * 64 + c + 1], c11);
            }
            yb[(long long)r0 * NDIM + c]     = tf32r(o00 + c00);
            yb[(long long)r0 * NDIM + c + 1] = tf32r(o01 + c01);
            yb[(long long)r1 * NDIM + c]     = tf32r(o10 + c10);
            yb[(long long)r1 * NDIM + c + 1] = tf32r(o11 + c11);
        }
    }
}

// ---------------- host orchestration ----------------
static float* sym(const void* p) { void* a = nullptr; cudaGetSymbolAddress(&a, p); return (float*)a; }

extern "C" void kernel_launch(void* const* d_in, const int* in_sizes, int n_in,
                              void* d_out, int out_size)
{
    const float* x      = (const float*)d_in[0];
    const float* w_qkv  = (const float*)d_in[1];
    const float* w_out  = (const float*)d_in[2];
    const float* b_out  = (const float*)d_in[3];
    const float* conv_w = (const float*)d_in[4];
    float* out = (float*)d_out;

    float* p_y  = sym(g_y);
    float* p_t  = sym(g_t);
    float* p_wo = sym(g_wout);

    static int attr_done = 0;
    if (!attr_done) {
        cudaFuncSetAttribute(attn2_fused_kernel,      cudaFuncAttributeMaxDynamicSharedMemorySize, 103000);
        cudaFuncSetAttribute(flash_a3v_tc_kernel,     cudaFuncAttributeMaxDynamicSharedMemorySize, 88100);
        cudaFuncSetAttribute(attn1_out_tc_kernel,     cudaFuncAttributeMaxDynamicSharedMemorySize, 88300);
        cudaFuncSetAttribute((const void*)tgemm_kernel<0, false>, cudaFuncAttributeMaxDynamicSharedMemorySize, 74000);
        cudaFuncSetAttribute((const void*)tgemm_kernel<2, true>,  cudaFuncAttributeMaxDynamicSharedMemorySize, 74000);
        cudaFuncSetAttribute(pinv_fused_kernel,       cudaFuncAttributeMaxDynamicSharedMemorySize, 72000);
        attr_done = 1;
    }
    size_t a2_smem = (4352 + 4352 + 16640 + 64) * sizeof(float);
    size_t fl_smem = (4352 + 8704 + 8704 + 256) * sizeof(float);          // 88,064
    size_t a1_smem = (4352 + 8704 + 8704 + 256 + 33 + 3) * sizeof(float); // 88,208
    size_t tg_smem = 4 * ASTG * sizeof(float);                            // 73,728
    size_t pv_smem = 2 * (ASTG + BSTG) * sizeof(float);                   // 71,680

    // 0. pre-round weights (w_qkv^T -> g_t; w_out^T -> g_wout); x rounded in-register
    round_tr_kernel<<<dim3(48, 16), 256>>>(p_t, w_qkv, 512, 1536);
    round_tr_kernel<<<dim3(16, 16), 256>>>(p_wo, w_out, 512, 512);

    // 1. QKV projection (A = raw x, cvt in registers; B = w_qkv^T)
    tgemm_kernel<2, true><<<dim3(12, 256, 1), 256, tg_smem>>>(
        x, p_t, nullptr, 512, 512, 512, 0, 1.f, nullptr, nullptr);

    // 2. landmark pooling
    pool_kernel<<<2048, 256>>>();

    // 3. attn2 = softmax(ql @ kl^T) + column partial sums
    attn2_fused_kernel<<<dim3(4, BH), 256, a2_smem>>>();

    // 4. pinv init (scale reduce + z0 transpose-init)
    pinv_scale_final<<<32, 256>>>();
    zinit_kernel<<<dim3(8, 8, 32), 256>>>();

    // 5. Newton-Schulz (fused; R14 proven config)
    pinv_fused_kernel<<<PINV_BLOCKS, 256, pv_smem>>>();

    // 6. a3v = softmax(ql @ k^T) @ v   (register-P flash)
    flash_a3v_tc_kernel<<<dim3(SPLIT, 4, BH), 256, fl_smem>>>();
    a3v_merge_kernel<<<2048, 256>>>();

    // 7. wm = z @ a3v
    gemm_wm_kernel<<<dim3(1, 4, BH), 256>>>();

    // 8. y = softmax(q @ kl^T) @ wm + conv(v)   (register-P attn1)
    attn1_out_tc_kernel<<<dim3(128, BH), 256, a1_smem>>>(conv_w);

    // 9. out = y @ w_out + b_out + x   (B = w_out^T)
    tgemm_kernel<0, false><<<dim3(4, 256, 1), 256, tg_smem>>>(
        p_y, p_wo, out, 512, 512, 512, 512, 1.f, b_out, x);
}